// round 5
// baseline (speedup 1.0000x reference)
#include <cuda_runtime.h>
#include <cuda_bf16.h>

#define DIM        128
#define MAX_ENT    50048
#define MAX_REL    24
#define MAX_NEEDED 4096
#define NBLK       148
#define NTHR       256
#define GSZ        (NBLK * NTHR)

// ---------------- device scratch (static zero-init == "clean" state) ------
// g_slot[node]: 0 = free, 1 = being claimed, s+2 = assigned slot s
__device__ int          g_slot[MAX_ENT];
__device__ int          g_needed_nodes[MAX_NEEDED];
__device__ int          g_n_needed;
__device__ unsigned int g_bar;     // monotonic grid-barrier counter
__device__ unsigned int g_done;    // exit counter
__device__ float        g_msg[(size_t)MAX_NEEDED * MAX_REL * DIM];
__device__ float        g_cnt[MAX_NEEDED * MAX_REL];
__device__ float        g_agg[MAX_NEEDED * DIM];

__device__ __forceinline__ int ld_idx(const void* p, size_t i, int is64) {
    if (is64) return (int)((const long long*)p)[i];
    return ((const int*)p)[i];
}

// fast tanh: 1 - 2/(e^{2x}+1)
__device__ __forceinline__ float ftanh(float x) {
    float e = __expf(2.0f * x);
    return 1.0f - 2.0f / (e + 1.0f);
}

// Monotonic-counter grid barrier (no reset -> no reuse race). All NBLK
// blocks are co-resident (grid == one wave), so spinning cannot deadlock.
__device__ __forceinline__ void grid_barrier(unsigned int target) {
    __threadfence();            // publish this thread's writes
    __syncthreads();
    if (threadIdx.x == 0) {
        atomicAdd(&g_bar, 1u);
        while (atomicAdd(&g_bar, 0u) < target) { }
        __threadfence();
    }
    __syncthreads();
}

// ---------------- the single fused persistent kernel ----------------------
__global__ void __launch_bounds__(NTHR)
k_fused(const float* __restrict__ x,
        const float* __restrict__ init_rel,
        const float* __restrict__ W_rel,
        const float* __restrict__ W_root,
        const void*  __restrict__ edge_index,
        const void*  __restrict__ edge_type,
        const void*  __restrict__ sample,
        float* __restrict__ out,
        int n_rel, int n_edge, int batch) {
    __shared__ float Ws[64 * DIM];   // one 64-col half of a W matrix
    __shared__ float ms[DIM];
    __shared__ int   s_any;

    const int tid  = threadIdx.x;
    const int bid  = blockIdx.x;
    const int gtid = bid * NTHR + tid;

    // ---- dtype detect (per block; int64 non-negative => high words all 0)
    if (tid == 0) s_any = 0;
    __syncthreads();
    if (((const unsigned int*)edge_index)[tid * 2 + 1] != 0u) atomicOr(&s_any, 1);
    __syncthreads();
    const int is64 = s_any ? 0 : 1;

    // ---- phase 1: mark + compact needed nodes from sample cols 0,2 -------
    for (int i = gtid; i < batch * 2; i += GSZ) {
        int b = i >> 1;
        int c = (i & 1) * 2;
        int node = ld_idx(sample, (size_t)b * 3 + c, is64);
        if (atomicCAS(&g_slot[node], 0, 1) == 0) {
            int s = atomicAdd(&g_n_needed, 1);
            g_needed_nodes[s] = node;
            g_slot[node] = s + 2;
        }
    }
    grid_barrier(1 * NBLK);

    const int nn = g_n_needed;

    // ---- phase 2: edge scan (4 edges/thread/iter, vectorized dst) --------
    {
        int nq = (n_edge + 3) >> 2;
        for (int q = gtid; q < nq; q += GSZ) {
            int e0 = q * 4;
            int nv = (e0 + 4 <= n_edge) ? 4 : (n_edge - e0);
            int dst[4];
            if (nv == 4) {
                if (!is64) {
                    int4 v = *(const int4*)((const int*)edge_index + (size_t)n_edge + e0);
                    dst[0] = v.x; dst[1] = v.y; dst[2] = v.z; dst[3] = v.w;
                } else {
                    longlong2 a = *(const longlong2*)((const long long*)edge_index + (size_t)n_edge + e0);
                    longlong2 b = *(const longlong2*)((const long long*)edge_index + (size_t)n_edge + e0 + 2);
                    dst[0] = (int)a.x; dst[1] = (int)a.y; dst[2] = (int)b.x; dst[3] = (int)b.y;
                }
            } else {
                for (int k = 0; k < nv; k++)
                    dst[k] = ld_idx(edge_index, (size_t)n_edge + e0 + k, is64);
            }
#pragma unroll
            for (int k = 0; k < 4; k++) {
                if (k >= nv) break;
                int s = g_slot[dst[k]] - 2;
                if (s < 0) continue;
                int e   = e0 + k;
                int r   = ld_idx(edge_type, e, is64);
                int src = ld_idx(edge_index, e, is64);
                atomicAdd(&g_cnt[s * n_rel + r], 1.0f);
                const float4* xs = (const float4*)(x + (size_t)src * DIM);
                float* m = &g_msg[((size_t)s * n_rel + r) * DIM];
#pragma unroll
                for (int j = 0; j < DIM / 4; j++) {
                    float4 v = xs[j];
                    atomicAdd(&m[4 * j + 0], v.x);
                    atomicAdd(&m[4 * j + 1], v.y);
                    atomicAdd(&m[4 * j + 2], v.z);
                    atomicAdd(&m[4 * j + 3], v.w);
                }
            }
        }
    }
    grid_barrier(2 * NBLK);

    // ---- phase 3: gemm. block -> one (r, half) work item ------------------
    // r < n_rel: msg_mean[s][r] @ W_rel[r];  r == n_rel: x[node] @ W_root.
    if (bid < (n_rel + 1) * 2) {
        int r    = bid % (n_rel + 1);
        int half = bid / (n_rel + 1);
        const float* W = (r < n_rel) ? (W_rel + (size_t)r * DIM * DIM) : W_root;
        int fbase = half * 64;

        for (int i = tid; i < 64 * DIM; i += NTHR) {
            int d = i >> 6, c = i & 63;
            Ws[i] = W[d * DIM + fbase + c];
        }
        __syncthreads();

        int c  = tid & 63;
        int dh = (tid >> 6) * 32;            // 4 groups x 32 d's

        for (int s = 0; s < nn; s++) {
            bool skip = false;
            float scale = 1.0f;
            if (r < n_rel) {
                float cnt = g_cnt[s * n_rel + r];   // uniform across block
                if (cnt == 0.0f) skip = true;
                else scale = 1.0f / cnt;
            }
            if (!skip && tid < DIM) {
                if (r < n_rel)
                    ms[tid] = g_msg[((size_t)s * n_rel + r) * DIM + tid] * scale;
                else
                    ms[tid] = x[(size_t)g_needed_nodes[s] * DIM + tid];
            }
            __syncthreads();
            if (!skip) {
                float acc = 0.0f;
#pragma unroll
                for (int k = 0; k < 8; k++) {
                    int d = dh + k * 4;
                    float4 mv = *(const float4*)&ms[d];
                    acc += mv.x * Ws[(d + 0) * 64 + c];
                    acc += mv.y * Ws[(d + 1) * 64 + c];
                    acc += mv.z * Ws[(d + 2) * 64 + c];
                    acc += mv.w * Ws[(d + 3) * 64 + c];
                }
                atomicAdd(&g_agg[s * DIM + fbase + c], acc);
            }
            __syncthreads();
        }
    }
    grid_barrier(3 * NBLK);

    // ---- phase 4: tanh in-place on agg (nn*DIM only) + msg/cnt zeroing ----
    for (int i = gtid; i < nn * DIM; i += GSZ) g_agg[i] = ftanh(g_agg[i]);
    {
        int n_msg = nn * n_rel * DIM;
        for (int i = gtid; i < n_msg; i += GSZ) g_msg[i] = 0.0f;
        int n_cnt = nn * n_rel;
        for (int i = gtid; i < n_cnt; i += GSZ) g_cnt[i] = 0.0f;
    }
    grid_barrier(4 * NBLK);

    // ---- phase 5: pure gather-multiply epilogue ---------------------------
    for (int i = gtid; i < batch * DIM; i += GSZ) {
        int b = i >> 7;
        int d = i & (DIM - 1);
        int h   = ld_idx(sample, (size_t)b * 3 + 0, is64);
        int rel = ld_idx(sample, (size_t)b * 3 + 1, is64);
        int t   = ld_idx(sample, (size_t)b * 3 + 2, is64);
        float hv = g_agg[(g_slot[h] - 2) * DIM + d];
        float tv = g_agg[(g_slot[t] - 2) * DIM + d];
        out[i] = hv * (init_rel[rel * DIM + d] * tv);
    }

    // ---- exit: signal done; block 0 alone restores clean state -----------
    __threadfence();
    __syncthreads();
    if (tid == 0) atomicAdd(&g_done, 1u);
    if (bid == 0) {
        if (tid == 0) {
            while (atomicAdd(&g_done, 0u) < NBLK) { }
            __threadfence();
        }
        __syncthreads();
        for (int i = tid; i < nn * DIM; i += NTHR) g_agg[i] = 0.0f;
        for (int i = tid; i < nn; i += NTHR) g_slot[g_needed_nodes[i]] = 0;
        __syncthreads();
        if (tid == 0) {
            g_n_needed = 0;
            g_bar  = 0u;
            g_done = 0u;
            __threadfence();
        }
    }
}

// ---------------- launch ----------------
extern "C" void kernel_launch(void* const* d_in, const int* in_sizes, int n_in,
                              void* d_out, int out_size) {
    const float* init_embed = (const float*)d_in[0];
    const float* init_rel   = (const float*)d_in[1];
    const float* W_rel      = (const float*)d_in[2];
    const float* W_root     = (const float*)d_in[3];
    const void*  edge_index = d_in[4];
    const void*  edge_type  = d_in[5];
    const void*  sample     = d_in[6];
    float* out = (float*)d_out;

    int n_rel  = in_sizes[1] / DIM;
    int n_edge = in_sizes[5];
    int batch  = in_sizes[6] / 3;

    k_fused<<<NBLK, NTHR>>>(init_embed, init_rel, W_rel, W_root,
                            edge_index, edge_type, sample, out,
                            n_rel, n_edge, batch);
}

// round 6
// speedup vs baseline: 1.9697x; 1.9697x over previous
#include <cuda_runtime.h>
#include <cuda_bf16.h>

#define DIM        128
#define MAX_ENT    50048
#define MAX_REL    24
#define MAX_NEEDED 4096
#define GROUPS     8

// ---------------- device scratch (static zero-init == "clean" state) ------
// g_slot[node]: 0 = free, 1 = being claimed, s+2 = assigned slot s
__device__ int          g_is64;
__device__ int          g_slot[MAX_ENT];
__device__ unsigned int g_bits[MAX_ENT / 32];        // membership bitmap
__device__ int          g_needed_nodes[MAX_NEEDED];
__device__ int          g_n_needed;
__device__ int          g_nn_copy;
__device__ float        g_msg[(size_t)MAX_NEEDED * MAX_REL * DIM];
__device__ float        g_cnt[MAX_NEEDED * MAX_REL];
__device__ float        g_agg[MAX_NEEDED * DIM];

__device__ __forceinline__ int ld_idx(const void* p, size_t i, int is64) {
    if (is64) return (int)((const long long*)p)[i];
    return ((const int*)p)[i];
}

// fast tanh: 1 - 2/(e^{2x}+1); rel err ~1e-7
__device__ __forceinline__ float ftanh(float x) {
    float e = __expf(2.0f * x);
    return 1.0f - 2.0f / (e + 1.0f);
}

// ---------------- 1) fused dtype-detect + mark + compact -------------------
__global__ void k_mark(const unsigned int* __restrict__ ei_words,
                       const void* __restrict__ sample, int batch) {
    __shared__ int s_any;
    if (threadIdx.x == 0) s_any = 0;
    __syncthreads();
    if (ei_words[threadIdx.x * 2 + 1] != 0u) atomicOr(&s_any, 1);
    __syncthreads();
    int is64 = s_any ? 0 : 1;
    if (blockIdx.x == 0 && threadIdx.x == 0) g_is64 = is64;

    int i = blockIdx.x * blockDim.x + threadIdx.x;
    if (i >= batch * 2) return;
    int b = i >> 1;
    int c = (i & 1) * 2;                       // sample columns 0 and 2
    int node = ld_idx(sample, (size_t)b * 3 + c, is64);
    if (atomicCAS(&g_slot[node], 0, 1) == 0) { // unique claimer assigns slot
        int s = atomicAdd(&g_n_needed, 1);
        g_needed_nodes[s] = node;
        atomicOr(&g_bits[node >> 5], 1u << (node & 31));
        g_slot[node] = s + 2;
    }
}

// ---------------- 2) edge scan: bitmap reject, 4 edges/thread --------------
__global__ void __launch_bounds__(256)
k_scan(const void* __restrict__ edge_index,
       const void* __restrict__ edge_type,
       const float* __restrict__ x,
       int n_edge, int n_rel) {
    int is64 = g_is64;
    int e0 = (blockIdx.x * blockDim.x + threadIdx.x) * 4;
    if (e0 >= n_edge) return;

    int dst[4];
    int nv = (e0 + 4 <= n_edge) ? 4 : (n_edge - e0);
    if (nv == 4) {
        if (!is64) {
            int4 v = *(const int4*)((const int*)edge_index + (size_t)n_edge + e0);
            dst[0] = v.x; dst[1] = v.y; dst[2] = v.z; dst[3] = v.w;
        } else {
            longlong2 a = *(const longlong2*)((const long long*)edge_index + (size_t)n_edge + e0);
            longlong2 b = *(const longlong2*)((const long long*)edge_index + (size_t)n_edge + e0 + 2);
            dst[0] = (int)a.x; dst[1] = (int)a.y; dst[2] = (int)b.x; dst[3] = (int)b.y;
        }
    } else {
        for (int k = 0; k < nv; k++)
            dst[k] = ld_idx(edge_index, (size_t)n_edge + e0 + k, is64);
    }

#pragma unroll
    for (int k = 0; k < 4; k++) {
        if (k >= nv) break;
        // cheap bitmap probe (6.3 KB working set) rejects ~99.95% of edges
        if (!(g_bits[dst[k] >> 5] & (1u << (dst[k] & 31)))) continue;
        int s = g_slot[dst[k]] - 2;
        int e   = e0 + k;
        int r   = ld_idx(edge_type, e, is64);
        int src = ld_idx(edge_index, e, is64);
        atomicAdd(&g_cnt[s * n_rel + r], 1.0f);
        const float4* xs = (const float4*)(x + (size_t)src * DIM);
        float* m = &g_msg[((size_t)s * n_rel + r) * DIM];
#pragma unroll
        for (int j = 0; j < DIM / 4; j++) {
            float4 v = xs[j];
            atomicAdd(&m[4 * j + 0], v.x);
            atomicAdd(&m[4 * j + 1], v.y);
            atomicAdd(&m[4 * j + 2], v.z);
            atomicAdd(&m[4 * j + 3], v.w);
        }
    }
}

// ---------------- 3) per-(rel, half, slot-group) GEMM -----------------------
// grid = (n_rel + 1) * 2 * GROUPS blocks of 128 threads.
__global__ void __launch_bounds__(128)
k_gemm(const float* __restrict__ W_rel,
       const float* __restrict__ W_root,
       const float* __restrict__ x,
       int n_rel) {
    __shared__ float Ws[64 * DIM];   // Ws[d * 64 + c]  (one 64-col half)
    __shared__ float ms[DIM];

    int idx  = blockIdx.x;
    int r    = idx % (n_rel + 1);
    int half = (idx / (n_rel + 1)) & 1;
    int sg   = idx / ((n_rel + 1) * 2);
    const float* W = (r < n_rel) ? (W_rel + (size_t)r * DIM * DIM) : W_root;
    int tid = threadIdx.x;
    int nn = g_n_needed;
    if (idx == 0 && tid == 0) g_nn_copy = nn;   // snapshot for out/cleanup

    int fbase = half * 64;
    // vectorized W staging: 16 float4 per thread
    for (int i = tid; i < 64 * DIM / 4; i += 128) {
        int d = i >> 4, c4 = i & 15;
        float4 v = *(const float4*)&W[d * DIM + fbase + c4 * 4];
        ((float4*)Ws)[d * 16 + c4] = v;
    }
    __syncthreads();

    int c  = tid & 63;
    int dh = (tid >> 6) * 64;

    for (int s = sg; s < nn; s += GROUPS) {
        bool skip = false;
        float scale = 1.0f;
        if (r < n_rel) {
            float cnt = g_cnt[s * n_rel + r];   // uniform across block
            if (cnt == 0.0f) skip = true;
            else scale = 1.0f / cnt;
        }
        if (!skip) {
            if (r < n_rel)
                ms[tid] = g_msg[((size_t)s * n_rel + r) * DIM + tid] * scale;
            else
                ms[tid] = x[(size_t)g_needed_nodes[s] * DIM + tid];
        }
        __syncthreads();
        if (!skip) {
            float acc = 0.0f;
#pragma unroll
            for (int k = 0; k < 16; k++) {
                int d = dh + k * 4;
                float4 mv = *(const float4*)&ms[d];
                acc += mv.x * Ws[(d + 0) * 64 + c];
                acc += mv.y * Ws[(d + 1) * 64 + c];
                acc += mv.z * Ws[(d + 2) * 64 + c];
                acc += mv.w * Ws[(d + 3) * 64 + c];
            }
            atomicAdd(&g_agg[s * DIM + fbase + c], acc);
        }
        __syncthreads();
    }
}

// ---------------- 4) warp-per-row gather epilogue + msg/cnt clean ----------
// grid: batch warps (8 warps/block). Lane = one float4 of the 128-dim row.
__global__ void __launch_bounds__(256)
k_out(const void* __restrict__ sample,
      const float* __restrict__ init_rel,
      float* __restrict__ out,
      int batch, int n_rel) {
    int gtid = blockIdx.x * blockDim.x + threadIdx.x;
    int gsz  = gridDim.x * blockDim.x;
    // absorb g_msg / g_cnt zeroing (gemm done; out doesn't read them)
    {
        int nn = g_nn_copy;
        int n_msg4 = nn * n_rel * (DIM / 4);
        float4 z = make_float4(0.f, 0.f, 0.f, 0.f);
        for (int i = gtid; i < n_msg4; i += gsz) ((float4*)g_msg)[i] = z;
        int n_cnt = nn * n_rel;
        for (int i = gtid; i < n_cnt; i += gsz) g_cnt[i] = 0.0f;
    }

    int w    = gtid >> 5;                  // warp id == batch row
    int lane = threadIdx.x & 31;
    if (w >= batch) return;

    int is64 = g_is64;
    int sh = 0, st = 0, rel = 0;
    if (lane == 0) {
        int h = ld_idx(sample, (size_t)w * 3 + 0, is64);
        rel   = ld_idx(sample, (size_t)w * 3 + 1, is64);
        int t = ld_idx(sample, (size_t)w * 3 + 2, is64);
        sh = g_slot[h] - 2;
        st = g_slot[t] - 2;
    }
    sh  = __shfl_sync(0xffffffffu, sh, 0);
    st  = __shfl_sync(0xffffffffu, st, 0);
    rel = __shfl_sync(0xffffffffu, rel, 0);

    float4 ah = ((const float4*)g_agg)[sh * (DIM / 4) + lane];
    float4 at = ((const float4*)g_agg)[st * (DIM / 4) + lane];
    float4 rv = ((const float4*)init_rel)[rel * (DIM / 4) + lane];
    float4 o;
    o.x = ftanh(ah.x) * (rv.x * ftanh(at.x));
    o.y = ftanh(ah.y) * (rv.y * ftanh(at.y));
    o.z = ftanh(ah.z) * (rv.z * ftanh(at.z));
    o.w = ftanh(ah.w) * (rv.w * ftanh(at.w));
    ((float4*)out)[(size_t)w * (DIM / 4) + lane] = o;
}

// ---------------- 5) tiny self-clean: agg + slot + bitmap + counters -------
__global__ void k_cleanup() {
    int nn = g_nn_copy;
    int tid = blockIdx.x * blockDim.x + threadIdx.x;
    int stride = gridDim.x * blockDim.x;
    for (int i = tid; i < nn * DIM; i += stride) g_agg[i] = 0.0f;
    for (int i = tid; i < nn; i += stride) {
        int node = g_needed_nodes[i];
        g_slot[node] = 0;
        g_bits[node >> 5] = 0u;   // every set bit belongs to a needed node
    }
    if (tid == 0) g_n_needed = 0;
}

// ---------------- launch ----------------
extern "C" void kernel_launch(void* const* d_in, const int* in_sizes, int n_in,
                              void* d_out, int out_size) {
    const float* init_embed = (const float*)d_in[0];
    const float* init_rel   = (const float*)d_in[1];
    const float* W_rel      = (const float*)d_in[2];
    const float* W_root     = (const float*)d_in[3];
    const void*  edge_index = d_in[4];
    const void*  edge_type  = d_in[5];
    const void*  sample     = d_in[6];
    float* out = (float*)d_out;

    int n_rel  = in_sizes[1] / DIM;
    int n_edge = in_sizes[5];
    int batch  = in_sizes[6] / 3;

    k_mark   <<<(batch * 2 + 255) / 256, 256>>>((const unsigned int*)edge_index,
                                                sample, batch);
    k_scan   <<<(n_edge + 4 * 256 - 1) / (4 * 256), 256>>>(edge_index, edge_type,
                                                           init_embed, n_edge, n_rel);
    k_gemm   <<<(n_rel + 1) * 2 * GROUPS, 128>>>(W_rel, W_root, init_embed, n_rel);
    k_out    <<<(batch * 32 + 255) / 256, 256>>>(sample, init_rel, out, batch, n_rel);
    k_cleanup<<<16, 256>>>();
}